// round 7
// baseline (speedup 1.0000x reference)
#include <cuda_runtime.h>
#include <cstdint>

#define N_CATS 8
#define NBLOCKS 592            // 4 CTAs/SM * 148 SMs
#define NTHREADS 256

// Device-global scratch: 8x8 confusion-matrix counts + arrival ticket.
// Zero at load; finalizing block resets them so every graph replay is clean.
__device__ unsigned int g_cm[64];
__device__ unsigned int g_done;

__device__ __forceinline__ int argmax8(float4 a, float4 b) {
    int best = 0; float m = a.x;
    if (a.y > m) { m = a.y; best = 1; }
    if (a.z > m) { m = a.z; best = 2; }
    if (a.w > m) { m = a.w; best = 3; }
    if (b.x > m) { m = b.x; best = 4; }
    if (b.y > m) { m = b.y; best = 5; }
    if (b.z > m) { m = b.z; best = 6; }
    if (b.w > m) { m = b.w; best = 7; }
    return best;
}

__global__ __launch_bounds__(NTHREADS, 4) void qwk_fused_kernel(
    const float4* __restrict__ logits4,   // 2 float4 per element
    const int* __restrict__ targets,      // int32
    float* __restrict__ out,
    int n_pairs)                          // n_elems / 2
{
    __shared__ unsigned int s_cm[64];
    __shared__ bool s_is_last;
    const int tid = threadIdx.x;
    const int lane = tid & 31;
    if (tid < 64) s_cm[tid] = 0u;
    __syncthreads();

    // Loop-invariant sign masks for this lane's two bins (lane and lane+32).
    unsigned sgn[5];
    #pragma unroll
    for (int k = 0; k < 5; k++)
        sgn[k] = (((unsigned)lane >> k) & 1u) - 1u;   // 1 -> 0x0, 0 -> 0xFFFFFFFF

    unsigned cL = 0u, cH = 0u;   // register counters: bins [lane], [lane+32]

    const int2* targets2 = (const int2*)targets;

    // Contiguous per-CTA chunk; block-stride inside. Each CTA streams one
    // linear region -> 592 sequential DRAM streams instead of 4736 scattered.
    const int chunk = (n_pairs + NBLOCKS - 1) / NBLOCKS;
    const int cta_beg = blockIdx.x * chunk;
    const int cta_end = min(cta_beg + chunk, n_pairs);

    for (int jb = cta_beg + tid; ; jb += NTHREADS) {
        // Warp-uniform continue condition (warp's first lane position).
        int jw = jb - lane;
        if (jw >= cta_end) break;

        bool inb = (jb < cta_end);
        int jc = inb ? jb : (cta_end - 1);   // clamp: safe load for tail lanes

        float4 a0 = __ldcs(&logits4[4 * jc + 0]);
        float4 b0 = __ldcs(&logits4[4 * jc + 1]);
        float4 a1 = __ldcs(&logits4[4 * jc + 2]);
        float4 b1 = __ldcs(&logits4[4 * jc + 3]);
        int2 tv2 = __ldcs(&targets2[jc]);

        int best0 = argmax8(a0, b0);
        int best1 = argmax8(a1, b1);

        unsigned bin0 = (unsigned)tv2.x * 8u + (unsigned)best0;
        unsigned bin1 = (unsigned)tv2.y * 8u + (unsigned)best1;
        bool v0 = inb && ((unsigned)(tv2.x - 1) < 7u);
        bool v1 = inb && ((unsigned)(tv2.y - 1) < 7u);

        // ---- ballot-histogram round 0 ----
        {
            unsigned m = __ballot_sync(0xffffffffu, v0);
            #pragma unroll
            for (int k = 0; k < 5; k++) {
                unsigned mb = __ballot_sync(0xffffffffu, (bin0 >> k) & 1u);
                m &= mb ^ sgn[k];
            }
            unsigned mb5 = __ballot_sync(0xffffffffu, (bin0 >> 5) & 1u);
            cL += __popc(m & ~mb5);
            cH += __popc(m & mb5);
        }
        // ---- round 1 ----
        {
            unsigned m = __ballot_sync(0xffffffffu, v1);
            #pragma unroll
            for (int k = 0; k < 5; k++) {
                unsigned mb = __ballot_sync(0xffffffffu, (bin1 >> k) & 1u);
                m &= mb ^ sgn[k];
            }
            unsigned mb5 = __ballot_sync(0xffffffffu, (bin1 >> 5) & 1u);
            cL += __popc(m & ~mb5);
            cH += __popc(m & mb5);
        }
    }

    // Per-warp flush: 2 shared atomics per lane, once per kernel.
    if (cL) atomicAdd(&s_cm[lane], cL);
    if (cH) atomicAdd(&s_cm[lane + 32], cH);
    __syncthreads();

    // Block flush to global.
    if (tid < 64) {
        unsigned int c = s_cm[tid];
        if (c) atomicAdd(&g_cm[tid], c);
    }

    // Ticket: last block to arrive finalizes.
    __threadfence();
    __syncthreads();
    if (tid == 0) {
        unsigned int rank = atomicAdd(&g_done, 1u);
        s_is_last = (rank == gridDim.x - 1);
    }
    __syncthreads();
    if (!s_is_last) return;

    if (tid == 0) {
        __threadfence();  // acquire: see all blocks' g_cm atomics

        float cm[64];
        float n = 0.0f;
        #pragma unroll
        for (int i = 0; i < 64; i++) {
            unsigned int c = atomicAdd(&g_cm[i], 0u);   // coherent read
            cm[i] = (float)c;
            n += cm[i];
        }

        float loss;
        if (n == 0.0f) {
            loss = 0.0f;   // qwk = 1 -> loss 0
        } else {
            float inv_n = 1.0f / n;
            #pragma unroll
            for (int i = 0; i < 64; i++) cm[i] *= inv_n;

            float mt[8], mp[8];
            #pragma unroll
            for (int i = 0; i < 8; i++) { mt[i] = 0.0f; mp[i] = 0.0f; }
            #pragma unroll
            for (int i = 0; i < 8; i++)
                #pragma unroll
                for (int jj = 0; jj < 8; jj++) {
                    mt[i] += cm[i * 8 + jj];
                    mp[jj] += cm[i * 8 + jj];
                }

            const float inv_d2 = 1.0f / 49.0f;
            float num = 0.0f, den = 0.0f;
            #pragma unroll
            for (int i = 0; i < 8; i++)
                #pragma unroll
                for (int jj = 0; jj < 8; jj++) {
                    float d = (float)(i - jj);
                    float w = 1.0f - d * d * inv_d2;
                    num += w * cm[i * 8 + jj];
                    den += w * mt[i] * mp[jj];
                }

            float qwk = (den == 0.0f) ? 0.0f : (num / den);
            loss = 1.0f - qwk;
        }
        out[0] = loss;

        // Reset scratch for the next graph replay.
        #pragma unroll
        for (int i = 0; i < 64; i++) g_cm[i] = 0u;
        g_done = 0u;
        __threadfence();
    }
}

extern "C" void kernel_launch(void* const* d_in, const int* in_sizes, int n_in,
                              void* d_out, int out_size) {
    const float4* logits4 = (const float4*)d_in[0];
    const int* targets = (const int*)d_in[1];
    float* out = (float*)d_out;
    int n_elems = in_sizes[1];       // B*S = 2048*4096 (even)
    int n_pairs = n_elems >> 1;

    qwk_fused_kernel<<<NBLOCKS, NTHREADS>>>(logits4, targets, out, n_pairs);
}

// round 8
// speedup vs baseline: 1.0349x; 1.0349x over previous
#include <cuda_runtime.h>
#include <cstdint>

#define N_CATS 8
#define NBLOCKS 592            // 4 CTAs/SM * 148 SMs
#define NTHREADS 256
#define NWARPS_TOTAL (NBLOCKS * (NTHREADS / 32))

// Device-global scratch: 8x8 confusion-matrix counts + arrival ticket.
__device__ unsigned int g_cm[64];
__device__ unsigned int g_done;

// Process one 32-element block held dense across the warp:
// lane l owns float4 A = logits4[2E + l], B = logits4[2E + 32 + l].
// Even lane finalizes element E + l/2 (from A pair); odd lane finalizes
// element E + 16 + (l-1)/2 (from B pair). tv is this lane's element's target.
__device__ __forceinline__ void process32(
    float4 A, float4 B, int tv, int lane,
    const unsigned* __restrict__ sgn, unsigned& cL, unsigned& cH)
{
    // Partial argmax within each float4 (first-max-wins)
    int aA = 0; float mA = A.x;
    if (A.y > mA) { mA = A.y; aA = 1; }
    if (A.z > mA) { mA = A.z; aA = 2; }
    if (A.w > mA) { mA = A.w; aA = 3; }
    int aB = 0; float mB = B.x;
    if (B.y > mB) { mB = B.y; aB = 1; }
    if (B.z > mB) { mB = B.z; aB = 2; }
    if (B.w > mB) { mB = B.w; aB = 3; }

    // Exchange partials with pair partner (lane ^ 1)
    float mAp = __shfl_xor_sync(0xffffffffu, mA, 1);
    int   aAp = __shfl_xor_sync(0xffffffffu, aA, 1);
    float mBp = __shfl_xor_sync(0xffffffffu, mB, 1);
    int   aBp = __shfl_xor_sync(0xffffffffu, aB, 1);

    // Even lane: own A = cats 0-3, partner A = cats 4-7 (hi wins on strict >).
    // Odd lane:  partner B = cats 0-3, own B = cats 4-7.
    int pred;
    if (lane & 1) pred = (mB  > mBp) ? (4 + aB)  : aBp;
    else          pred = (mAp > mA ) ? (4 + aAp) : aA;

    unsigned bin = (unsigned)tv * 8u + (unsigned)pred;
    bool v = ((unsigned)(tv - 1) < 7u);

    unsigned m = __ballot_sync(0xffffffffu, v);
    #pragma unroll
    for (int k = 0; k < 5; k++) {
        unsigned mb = __ballot_sync(0xffffffffu, (bin >> k) & 1u);
        m &= mb ^ sgn[k];
    }
    unsigned mb5 = __ballot_sync(0xffffffffu, (bin >> 5) & 1u);
    cL += __popc(m & ~mb5);
    cH += __popc(m & mb5);
}

__global__ __launch_bounds__(NTHREADS, 4) void qwk_fused_kernel(
    const float4* __restrict__ logits4,   // 2 float4 per element
    const int* __restrict__ targets,      // int32
    float* __restrict__ out,
    int n_elems)                          // B*S, multiple of 64
{
    __shared__ unsigned int s_cm[64];
    __shared__ bool s_is_last;
    const int tid = threadIdx.x;
    const int lane = tid & 31;
    if (tid < 64) s_cm[tid] = 0u;
    __syncthreads();

    // Loop-invariant sign masks for this lane's two bins (lane, lane+32).
    unsigned sgn[5];
    #pragma unroll
    for (int k = 0; k < 5; k++)
        sgn[k] = (((unsigned)lane >> k) & 1u) - 1u;   // bit=1 -> 0x0, bit=0 -> ~0

    unsigned cL = 0u, cH = 0u;

    const int warp_global = blockIdx.x * (NTHREADS / 32) + (tid >> 5);
    const int stride = NWARPS_TOTAL * 64;              // elements per grid step
    // Lane -> element offset within a 32-block: even l -> l/2, odd l -> 16+(l-1)/2
    const int el_off = (lane >> 1) + ((lane & 1) << 4);

    for (int E = warp_global * 64; E < n_elems; E += stride) {
        const float4* p = logits4 + (size_t)2 * E;
        // Front-batched dense loads: 4x LDG.128 (nL=4) + 2x LDG.32 (nL=1)
        float4 A0 = __ldcs(p + lane);
        float4 B0 = __ldcs(p + 32 + lane);
        float4 A1 = __ldcs(p + 64 + lane);
        float4 B1 = __ldcs(p + 96 + lane);
        int t0 = __ldcs(targets + E + el_off);
        int t1 = __ldcs(targets + E + 32 + el_off);

        process32(A0, B0, t0, lane, sgn, cL, cH);
        process32(A1, B1, t1, lane, sgn, cL, cH);
    }

    // Per-warp flush: 2 shared atomics per lane, once per kernel.
    if (cL) atomicAdd(&s_cm[lane], cL);
    if (cH) atomicAdd(&s_cm[lane + 32], cH);
    __syncthreads();

    // Block flush to global.
    if (tid < 64) {
        unsigned int c = s_cm[tid];
        if (c) atomicAdd(&g_cm[tid], c);
    }

    // Ticket: last block to arrive finalizes.
    __threadfence();
    __syncthreads();
    if (tid == 0) {
        unsigned int rank = atomicAdd(&g_done, 1u);
        s_is_last = (rank == gridDim.x - 1);
    }
    __syncthreads();
    if (!s_is_last) return;

    if (tid == 0) {
        __threadfence();  // acquire: see all blocks' g_cm atomics

        float cm[64];
        float n = 0.0f;
        #pragma unroll
        for (int i = 0; i < 64; i++) {
            unsigned int c = atomicAdd(&g_cm[i], 0u);   // coherent read
            cm[i] = (float)c;
            n += cm[i];
        }

        float loss;
        if (n == 0.0f) {
            loss = 0.0f;   // qwk = 1 -> loss 0
        } else {
            float inv_n = 1.0f / n;
            #pragma unroll
            for (int i = 0; i < 64; i++) cm[i] *= inv_n;

            float mt[8], mp[8];
            #pragma unroll
            for (int i = 0; i < 8; i++) { mt[i] = 0.0f; mp[i] = 0.0f; }
            #pragma unroll
            for (int i = 0; i < 8; i++)
                #pragma unroll
                for (int jj = 0; jj < 8; jj++) {
                    mt[i] += cm[i * 8 + jj];
                    mp[jj] += cm[i * 8 + jj];
                }

            const float inv_d2 = 1.0f / 49.0f;
            float num = 0.0f, den = 0.0f;
            #pragma unroll
            for (int i = 0; i < 8; i++)
                #pragma unroll
                for (int jj = 0; jj < 8; jj++) {
                    float d = (float)(i - jj);
                    float w = 1.0f - d * d * inv_d2;
                    num += w * cm[i * 8 + jj];
                    den += w * mt[i] * mp[jj];
                }

            float qwk = (den == 0.0f) ? 0.0f : (num / den);
            loss = 1.0f - qwk;
        }
        out[0] = loss;

        // Reset scratch for the next graph replay.
        #pragma unroll
        for (int i = 0; i < 64; i++) g_cm[i] = 0u;
        g_done = 0u;
        __threadfence();
    }
}

extern "C" void kernel_launch(void* const* d_in, const int* in_sizes, int n_in,
                              void* d_out, int out_size) {
    const float4* logits4 = (const float4*)d_in[0];
    const int* targets = (const int*)d_in[1];
    float* out = (float*)d_out;
    int n_elems = in_sizes[1];       // 2048*4096, multiple of 64

    qwk_fused_kernel<<<NBLOCKS, NTHREADS>>>(logits4, targets, out, n_elems);
}